// round 14
// baseline (speedup 1.0000x reference)
#include <cuda_runtime.h>
#include <math.h>
#include <stdint.h>

#define NN   32768
#define EE   1048576
#define NSD  64
#define NVD  32
#define LATD 256

// ---- scales ----
#define INV8    0.125f                 // 1/sqrt(64)
#define C1      0.10206207261596575f   // (1/sqrt(3))/sqrt(32) = 1/sqrt(96)
#define INV_R2  0.7071067811865476f
#define INVS32  0.17677669529663687f   // 1/sqrt(32)
#define S_USS   0.011048543456039806f  // 1/(64*sqrt(2))
#define S_UVV   0.012757998811063534f  // 1/(32*sqrt(6))
#define S_V     0.015625f              // 1/sqrt(64*32*2) = 1/64

typedef unsigned long long ull;

// ---- scratch (device globals; no allocation) ----
__device__ float g_ns[NN * NSD];
__device__ float g_nv[NN * NVD * 3];
__device__ float g_NF[(size_t)NN * 384];  // SS(64)|Q(3x64)|SV(32)|VS(3x32)
__device__ float g_as[NN * NSD];
__device__ float g_av[NN * NVD * 3];

__device__ __forceinline__ float sigmf(float x) { return 1.0f / (1.0f + __expf(-x)); }

// ---- packed f32x2 helpers ----
__device__ __forceinline__ void ffma2(ull& d, ull a, ull b) {
    asm("fma.rn.f32x2 %0, %1, %2, %0;" : "+l"(d) : "l"(a), "l"(b));
}
__device__ __forceinline__ ull fadd2(ull a, ull b) {
    ull r; asm("add.rn.f32x2 %0, %1, %2;" : "=l"(r) : "l"(a), "l"(b)); return r;
}
__device__ __forceinline__ ull pack2(float x, float y) {
    ull r;
    asm("mov.b64 %0, {%1, %2};" : "=l"(r)
        : "r"(__float_as_uint(x)), "r"(__float_as_uint(y)));
    return r;
}
__device__ __forceinline__ float2 unpack2(ull v) {
    unsigned int lo, hi;
    asm("mov.b64 {%0, %1}, %2;" : "=r"(lo), "=r"(hi) : "l"(v));
    return make_float2(__uint_as_float(lo), __uint_as_float(hi));
}

// ============================ k_in: ns = x @ W_in / 8 ============================
__global__ __launch_bounds__(256) void k_in(const float* __restrict__ x,
                                            const float* __restrict__ Win) {
    __shared__ float xs[32 * 65];
    __shared__ float ws[64 * 64];
    const int tid = threadIdx.x;
    const int node0 = blockIdx.x * 32;
    const float4* wg = (const float4*)Win;
    float4* ws4 = (float4*)ws;
#pragma unroll
    for (int r = 0; r < 4; r++) ws4[tid + r * 256] = wg[tid + r * 256];
#pragma unroll
    for (int r = 0; r < 8; r++) {
        int lin = tid + r * 256; int t = lin >> 6, i = lin & 63;
        xs[t * 65 + i] = x[(size_t)(node0 + t) * 64 + i];
    }
    __syncthreads();
    const int o = tid & 63, tq = tid >> 6;
    float acc[8] = {0, 0, 0, 0, 0, 0, 0, 0};
#pragma unroll 16
    for (int i = 0; i < 64; i++) {
        float w = ws[i * 64 + o];
#pragma unroll
        for (int tt = 0; tt < 8; tt++) acc[tt] += xs[(tq * 8 + tt) * 65 + i] * w;
    }
#pragma unroll
    for (int tt = 0; tt < 8; tt++)
        g_ns[(size_t)(node0 + tq * 8 + tt) * 64 + o] = acc[tt] * INV8;
}

// ============== k_feat: per-node precompute SS, Q, SV, VS ==============
__global__ __launch_bounds__(256) void k_feat(const float* __restrict__ Wss,
                                              const float* __restrict__ Wvv0,
                                              const float* __restrict__ Wsv,
                                              const float* __restrict__ Wvs) {
    __shared__ float s_wss[64 * 64];
    __shared__ float s_wvv[32 * 64];
    __shared__ float s_wsv[64 * 32];
    __shared__ float s_wvs[32 * 32];
    __shared__ float s_ns[8][64];
    __shared__ float s_nv[8][96];
    const int tid = threadIdx.x;
    for (int i = tid; i < 4096; i += 256) s_wss[i] = Wss[i];
    for (int i = tid; i < 2048; i += 256) s_wvv[i] = Wvv0[i];
    for (int i = tid; i < 2048; i += 256) s_wsv[i] = Wsv[i];
    for (int i = tid; i < 1024; i += 256) s_wvs[i] = Wvs[i];
    const int w = tid >> 5, lane = tid & 31;
    const int node = blockIdx.x * 8 + w;
#pragma unroll
    for (int r = 0; r < 2; r++) s_ns[w][lane + 32 * r] = g_ns[(size_t)node * 64 + lane + 32 * r];
#pragma unroll
    for (int r = 0; r < 3; r++) s_nv[w][lane + 32 * r] = g_nv[(size_t)node * 96 + lane + 32 * r];
    __syncthreads();
    float* nf = g_NF + (size_t)node * 384;
#pragma unroll
    for (int h = 0; h < 2; h++) {
        int o = lane + 32 * h;
        float a = 0;
#pragma unroll 8
        for (int i = 0; i < 64; i++) a += s_ns[w][i] * s_wss[i * 64 + o];
        nf[o] = a;
    }
#pragma unroll
    for (int xx = 0; xx < 3; xx++) {
#pragma unroll
        for (int h = 0; h < 2; h++) {
            int o = lane + 32 * h;
            float a = 0;
#pragma unroll 8
            for (int m = 0; m < 32; m++) a += s_nv[w][m * 3 + xx] * s_wvv[m * 64 + o];
            nf[64 + xx * 64 + o] = a;
        }
    }
    {
        float a = 0;
#pragma unroll 8
        for (int i = 0; i < 64; i++) a += s_ns[w][i] * s_wsv[i * 32 + lane];
        nf[256 + lane] = a;
    }
#pragma unroll
    for (int xx = 0; xx < 3; xx++) {
        float a = 0;
#pragma unroll 8
        for (int m = 0; m < 32; m++) a += s_nv[w][m * 3 + xx] * s_wvs[m * 32 + lane];
        nf[288 + xx * 32 + lane] = a;
    }
}

// ================= k_edge: per-edge message + gate + scatter-add =================
__global__ __launch_bounds__(256) void k_edge(const float* __restrict__ eattr,
                                              const int* __restrict__ eidx,
                                              const float* __restrict__ gmw,
                                              const float* __restrict__ gmb) {
    __shared__ float s_gw[96], s_gb[96];
    const int tid = threadIdx.x;
    if (tid < 96) { s_gw[tid] = gmw[tid]; s_gb[tid] = gmb[tid]; }
    __syncthreads();
    const int w = tid >> 5, lane = tid & 31;
    const int e = blockIdx.x * 8 + w;
    const int r = eidx[e];
    const int c = eidx[EE + e];
    const float ev0 = eattr[(size_t)e * 4 + 0];
    const float ev1 = eattr[(size_t)e * 4 + 1];
    const float ev2 = eattr[(size_t)e * 4 + 2];
    const float es  = eattr[(size_t)e * 4 + 3];
    const float* nf = g_NF + (size_t)c * 384;
    float ms[2];
#pragma unroll
    for (int h = 0; h < 2; h++) {
        int o = lane + 32 * h;
        float dot = ev0 * nf[64 + o] + ev1 * nf[128 + o] + ev2 * nf[192 + o];
        float v = (es * nf[o] * INV8 + dot * C1) * INV_R2;
        ms[h] = v * sigmf(v);
    }
    const float sv = nf[256 + lane];
    float mv0 = (sv * ev0 * INV8 + es * nf[288 + lane] * INVS32) * INV_R2;
    float mv1 = (sv * ev1 * INV8 + es * nf[320 + lane] * INVS32) * INV_R2;
    float mv2 = (sv * ev2 * INV8 + es * nf[352 + lane] * INVS32) * INV_R2;
    float p = mv0 + mv1 + mv2;
#pragma unroll
    for (int off = 16; off; off >>= 1) p += __shfl_xor_sync(0xffffffffu, p, off);
    const float mean = p * (1.0f / 96.0f);
    const float g0 = sigmf(mean * s_gw[lane * 3 + 0] + s_gb[lane * 3 + 0]);
    const float g1 = sigmf(mean * s_gw[lane * 3 + 1] + s_gb[lane * 3 + 1]);
    const float g2 = sigmf(mean * s_gw[lane * 3 + 2] + s_gb[lane * 3 + 2]);
    float* as = g_as + (size_t)r * 64;
    float* av = g_av + (size_t)r * 96;
    atomicAdd(as + lane,        ms[0]);
    atomicAdd(as + lane + 32,   ms[1]);
    atomicAdd(av + lane * 3 + 0, mv0 * g0);
    atomicAdd(av + lane * 3 + 1, mv1 * g1);
    atomicAdd(av + lane * 3 + 2, mv2 * g2);
}

// ====== k_bilin: four bilinears + gate + residual ======
// 64 nodes / block, 256 threads, 2 blocks/SM. R10 skeleton (kb=32, stage/sync/compute/sync).
// Phase A retiled: 8 outs x 4 nodes x half-K per thread; f32x2 lanes = OUT PAIR
// (W read directly as ull pairs, A broadcast-packed). Half-K partials reduced via smem.
// Phase B identical to R10.
// smem floats: ns 4160 | as 4160 | nv 6208 | av 6208 | scr 7168 = 27904 (109KB)
#define BILIN_SMEM (27904 * 4)

__global__ __launch_bounds__(256, 2) void k_bilin(const float* __restrict__ Wuss,
                                                  const float* __restrict__ Wuvv,
                                                  const float* __restrict__ Wusv,
                                                  const float* __restrict__ Wuvs,
                                                  const float* __restrict__ guw,
                                                  const float* __restrict__ gub) {
    extern __shared__ float sm[];
    float* ns_s = sm;                 // [64][65]
    float* as_s = sm + 4160;          // [64][65]
    float* nv_s = sm + 8320;          // [64][97]
    float* av_s = sm + 14528;         // [64][97]
    float* scr  = sm + 20736;         // 7168 floats (W + A staging, reused per phase)
    const int tid = threadIdx.x;
    const int node0 = blockIdx.x * 64;

    // ---- load node data (vectorized) ----
    {
        const float4* gns = (const float4*)(g_ns + (size_t)node0 * 64);
        const float4* gas = (const float4*)(g_as + (size_t)node0 * 64);
#pragma unroll
        for (int r = 0; r < 4; r++) {
            int lin = tid + r * 256; int t = lin >> 4, c = lin & 15;
            float4 v = gns[lin];
            float4 u = gas[lin];
            float* pd = ns_s + t * 65 + c * 4;
            pd[0] = v.x; pd[1] = v.y; pd[2] = v.z; pd[3] = v.w;
            float* qd = as_s + t * 65 + c * 4;
            qd[0] = u.x; qd[1] = u.y; qd[2] = u.z; qd[3] = u.w;
        }
        const float4* gnv = (const float4*)(g_nv + (size_t)node0 * 96);
        const float4* gav = (const float4*)(g_av + (size_t)node0 * 96);
#pragma unroll
        for (int r = 0; r < 6; r++) {
            int lin = tid + r * 256; int t = lin / 24, c = lin % 24;
            float4 v = gnv[lin];
            float4 u = gav[lin];
            float* pd = nv_s + t * 97 + c * 4;
            pd[0] = v.x; pd[1] = v.y; pd[2] = v.z; pd[3] = v.w;
            float* qd = av_s + t * 97 + c * 4;
            qd[0] = u.x; qd[1] = u.y; qd[2] = u.z; qd[3] = u.w;
        }
    }
    __syncthreads();

    // ================ Phase A: u_s = uss + uvv ================
    // thread tile: 8 outs (txA, as 4 out-pairs in f32x2 lanes) x 4 nodes (tyA) x half-K (khA)
    const int txA = tid & 7;           // outs 8*txA .. 8*txA+7
    const int tyA = (tid >> 3) & 15;   // nodes 4*tyA .. 4*tyA+3
    const int khA = tid >> 7;          // K half: kk in [16*khA, 16*khA+16)
    float* W_s = scr;            // [32][64], pre-scaled
    float* A_s = scr + 2048;     // [32][64]
    ull acc[16];                 // acc[p*4+n]: out-pair p (outs 2p,2p+1 within group), node n
#pragma unroll
    for (int q = 0; q < 16; q++) acc[q] = 0ull;

    auto COMPUTE_A = [&](const float* Ws, const float* As) {
#pragma unroll 8
        for (int kq = 0; kq < 16; kq++) {
            const int kk = khA * 16 + kq;
            float4 a4 = *(const float4*)(As + kk * 64 + tyA * 4);
            ulonglong2 wA = *(const ulonglong2*)(Ws + kk * 64 + txA * 8);
            ulonglong2 wB = *(const ulonglong2*)(Ws + kk * 64 + txA * 8 + 4);
            ull an0 = pack2(a4.x, a4.x), an1 = pack2(a4.y, a4.y);
            ull an2 = pack2(a4.z, a4.z), an3 = pack2(a4.w, a4.w);
            ffma2(acc[0],  an0, wA.x); ffma2(acc[1],  an1, wA.x);
            ffma2(acc[2],  an2, wA.x); ffma2(acc[3],  an3, wA.x);
            ffma2(acc[4],  an0, wA.y); ffma2(acc[5],  an1, wA.y);
            ffma2(acc[6],  an2, wA.y); ffma2(acc[7],  an3, wA.y);
            ffma2(acc[8],  an0, wB.x); ffma2(acc[9],  an1, wB.x);
            ffma2(acc[10], an2, wB.x); ffma2(acc[11], an3, wB.x);
            ffma2(acc[12], an0, wB.y); ffma2(acc[13], an1, wB.y);
            ffma2(acc[14], an2, wB.y); ffma2(acc[15], an3, wB.y);
        }
    };

    // --- uss: K = 4096, A[t,k] = ns[t,i]*as[t,j], k=(i<<6)|j ---
    for (int kb = 0; kb < 4096; kb += 32) {
        const float4* wg = (const float4*)(Wuss + (size_t)kb * 64);
        float4* ws4 = (float4*)W_s;
#pragma unroll
        for (int rr = 0; rr < 2; rr++) {
            float4 w = wg[tid + rr * 256];
            w.x *= S_USS; w.y *= S_USS; w.z *= S_USS; w.w *= S_USS;
            ws4[tid + rr * 256] = w;
        }
#pragma unroll
        for (int rr = 0; rr < 8; rr++) {
            int lin = tid + rr * 256; int kk = lin >> 6, t = lin & 63;
            int k = kb + kk; int i = k >> 6, j = k & 63;
            A_s[kk * 64 + t] = ns_s[t * 65 + i] * as_s[t * 65 + j];
        }
        __syncthreads();
        COMPUTE_A(W_s, A_s);
        __syncthreads();
    }
    // --- uvv: K = 3*1024 (x outer), A = nv[t,m,x]*av[t,n,x], k=(m<<5)|n ---
    for (int kb = 0; kb < 3072; kb += 32) {
        int xx = kb >> 10, km = kb & 1023;
        const float4* wg = (const float4*)(Wuvv + (size_t)km * 64);
        float4* ws4 = (float4*)W_s;
#pragma unroll
        for (int rr = 0; rr < 2; rr++) {
            float4 w = wg[tid + rr * 256];
            w.x *= S_UVV; w.y *= S_UVV; w.z *= S_UVV; w.w *= S_UVV;
            ws4[tid + rr * 256] = w;
        }
#pragma unroll
        for (int rr = 0; rr < 8; rr++) {
            int lin = tid + rr * 256; int kk = lin >> 6, t = lin & 63;
            int k = km + kk; int m = k >> 5, n = k & 31;
            A_s[kk * 64 + t] = nv_s[t * 97 + m * 3 + xx] * av_s[t * 97 + n * 3 + xx];
        }
        __syncthreads();
        COMPUTE_A(W_s, A_s);
        __syncthreads();
    }

    // ---- half-K reduction: kh=1 dumps partials, kh=0 adds + epilogue ----
    {
        ull* red = (ull*)scr;    // 128 threads x 16 ull = 2048 ull = 4096 floats (fits 7168)
        if (khA == 1) {
            const int base = (tid & 127) * 16;
#pragma unroll
            for (int q = 0; q < 16; q++) red[base + q] = acc[q];
        }
        __syncthreads();
        if (khA == 0) {
            const int base = tid * 16;
#pragma unroll
            for (int q = 0; q < 16; q++) acc[q] = fadd2(acc[q], red[base + q]);
            // u_s epilogue: silu + residual -> global ns (ns_s stays intact for phase B)
#pragma unroll
            for (int n = 0; n < 4; n++) {
                const int t = tyA * 4 + n;
                float* gp = g_ns + (size_t)(node0 + t) * 64 + txA * 8;
#pragma unroll
                for (int p = 0; p < 4; p++) {
                    float2 u = unpack2(acc[p * 4 + n]);
                    const int o0 = txA * 8 + 2 * p;
                    float2 w;
                    w.x = ns_s[t * 65 + o0]     + u.x * sigmf(u.x);
                    w.y = ns_s[t * 65 + o0 + 1] + u.y * sigmf(u.y);
                    *(float2*)(gp + 2 * p) = w;
                }
            }
        }
        __syncthreads();   // protect scr before phase B staging reuses it
    }

    // ================ Phase B: u_v = usv + uvs (identical to R10) ================
    // thread tile: 4 outs (txB) x 2 nodes (f32x2 pair, tyB) x 3 x-components
    const int txB = tid & 7, tyB = tid >> 3;
    float* WB = scr;             // [32][32], pre-scaled
    float* AB = scr + 1024;      // [3][32][64]
    ull vacc[12];
#pragma unroll
    for (int q = 0; q < 12; q++) vacc[q] = 0ull;

    // --- usv: K = 2048 per x, A(x)[t,k] = ns[t,i]*av[t,n,x], k=(i<<5)|n ---
    for (int kb = 0; kb < 2048; kb += 32) {
        {
            float4 w = ((const float4*)(Wusv + (size_t)kb * 32))[tid];
            w.x *= S_V; w.y *= S_V; w.z *= S_V; w.w *= S_V;
            ((float4*)WB)[tid] = w;
        }
#pragma unroll
        for (int rr = 0; rr < 24; rr++) {
            int lin = tid + rr * 256;
            int xx = lin >> 11; int rem = lin & 2047; int kk = rem >> 6, t = rem & 63;
            int k = kb + kk; int i = k >> 5, n = k & 31;
            AB[xx * 2048 + kk * 64 + t] = ns_s[t * 65 + i] * av_s[t * 97 + n * 3 + xx];
        }
        __syncthreads();
#pragma unroll 8
        for (int kk = 0; kk < 32; kk++) {
            float4 w4 = *(const float4*)(WB + kk * 32 + txB * 4);
            ull w0 = pack2(w4.x, w4.x), w1 = pack2(w4.y, w4.y);
            ull w2 = pack2(w4.z, w4.z), w3 = pack2(w4.w, w4.w);
            ull a0 = *(const ull*)(AB + kk * 64 + tyB * 2);
            ull a1 = *(const ull*)(AB + 2048 + kk * 64 + tyB * 2);
            ull a2 = *(const ull*)(AB + 4096 + kk * 64 + tyB * 2);
            ffma2(vacc[0],  a0, w0); ffma2(vacc[1],  a0, w1);
            ffma2(vacc[2],  a0, w2); ffma2(vacc[3],  a0, w3);
            ffma2(vacc[4],  a1, w0); ffma2(vacc[5],  a1, w1);
            ffma2(vacc[6],  a1, w2); ffma2(vacc[7],  a1, w3);
            ffma2(vacc[8],  a2, w0); ffma2(vacc[9],  a2, w1);
            ffma2(vacc[10], a2, w2); ffma2(vacc[11], a2, w3);
        }
        __syncthreads();
    }
    // --- uvs: K = 2048 per x, A(x)[t,k] = nv[t,m,x]*as[t,j], k=(m<<6)|j ---
    for (int kb = 0; kb < 2048; kb += 32) {
        {
            float4 w = ((const float4*)(Wuvs + (size_t)kb * 32))[tid];
            w.x *= S_V; w.y *= S_V; w.z *= S_V; w.w *= S_V;
            ((float4*)WB)[tid] = w;
        }
#pragma unroll
        for (int rr = 0; rr < 24; rr++) {
            int lin = tid + rr * 256;
            int xx = lin >> 11; int rem = lin & 2047; int kk = rem >> 6, t = rem & 63;
            int k = kb + kk; int m = k >> 6, j = k & 63;
            AB[xx * 2048 + kk * 64 + t] = nv_s[t * 97 + m * 3 + xx] * as_s[t * 65 + j];
        }
        __syncthreads();
#pragma unroll 8
        for (int kk = 0; kk < 32; kk++) {
            float4 w4 = *(const float4*)(WB + kk * 32 + txB * 4);
            ull w0 = pack2(w4.x, w4.x), w1 = pack2(w4.y, w4.y);
            ull w2 = pack2(w4.z, w4.z), w3 = pack2(w4.w, w4.w);
            ull a0 = *(const ull*)(AB + kk * 64 + tyB * 2);
            ull a1 = *(const ull*)(AB + 2048 + kk * 64 + tyB * 2);
            ull a2 = *(const ull*)(AB + 4096 + kk * 64 + tyB * 2);
            ffma2(vacc[0],  a0, w0); ffma2(vacc[1],  a0, w1);
            ffma2(vacc[2],  a0, w2); ffma2(vacc[3],  a0, w3);
            ffma2(vacc[4],  a1, w0); ffma2(vacc[5],  a1, w1);
            ffma2(vacc[6],  a1, w2); ffma2(vacc[7],  a1, w3);
            ffma2(vacc[8],  a2, w0); ffma2(vacc[9],  a2, w1);
            ffma2(vacc[10], a2, w2); ffma2(vacc[11], a2, w3);
        }
        __syncthreads();
    }

    // u_v epilogue: mean over 96 per node (8 threads share pair tyB), gate, residual
    {
        ull psum = vacc[0];
#pragma unroll
        for (int q = 1; q < 12; q++) psum = fadd2(psum, vacc[q]);
        psum = fadd2(psum, __shfl_xor_sync(0xffffffffu, psum, 1));
        psum = fadd2(psum, __shfl_xor_sync(0xffffffffu, psum, 2));
        psum = fadd2(psum, __shfl_xor_sync(0xffffffffu, psum, 4));
        float2 pm = unpack2(psum);
        const float mean0 = pm.x * (1.0f / 96.0f);
        const float mean1 = pm.y * (1.0f / 96.0f);
        const int n0 = tyB * 2;
#pragma unroll
        for (int xx = 0; xx < 3; xx++) {
#pragma unroll
            for (int q = 0; q < 4; q++) {
                int o = txB * 4 + q; int idx = o * 3 + xx;
                float gw = __ldg(guw + idx), gb = __ldg(gub + idx);
                float2 u = unpack2(vacc[xx * 4 + q]);
                float g0 = sigmf(mean0 * gw + gb);
                float g1 = sigmf(mean1 * gw + gb);
                g_nv[(size_t)(node0 + n0) * 96 + idx]     = nv_s[n0 * 97 + idx] + u.x * g0;
                g_nv[(size_t)(node0 + n0 + 1) * 96 + idx] = nv_s[(n0 + 1) * 97 + idx] + u.y * g1;
            }
        }
    }
}

// ============================ k_out: out = ns @ W_out / 8 ============================
__global__ __launch_bounds__(256) void k_out(const float* __restrict__ Wout,
                                             float* __restrict__ out) {
    __shared__ float s_w[32 * 256];
    __shared__ float s_ns[16 * 64];
    const int tid = threadIdx.x;
    const int node0 = blockIdx.x * 16;
#pragma unroll
    for (int r = 0; r < 4; r++) {
        int lin = tid + r * 256; int t = lin >> 6, i = lin & 63;
        s_ns[t * 64 + i] = g_ns[(size_t)(node0 + t) * 64 + i];
    }
    float acc[16];
#pragma unroll
    for (int t = 0; t < 16; t++) acc[t] = 0.f;
    for (int ic = 0; ic < 2; ic++) {
        __syncthreads();
        const float4* wg = (const float4*)(Wout + (size_t)ic * 32 * 256);
        float4* ws4 = (float4*)s_w;
#pragma unroll
        for (int r = 0; r < 8; r++) ws4[tid + r * 256] = wg[tid + r * 256];
        __syncthreads();
#pragma unroll 8
        for (int i = 0; i < 32; i++) {
            float w = s_w[i * 256 + tid];
#pragma unroll
            for (int t = 0; t < 16; t++) acc[t] += s_ns[t * 64 + ic * 32 + i] * w;
        }
    }
#pragma unroll
    for (int t = 0; t < 16; t++)
        out[(size_t)(node0 + t) * 256 + tid] = acc[t] * INV8;
}

// =====================================================================================
extern "C" void kernel_launch(void* const* d_in, const int* in_sizes, int n_in,
                              void* d_out, int out_size) {
    const float* x    = (const float*)d_in[0];
    const float* eattr= (const float*)d_in[1];
    const float* Win  = (const float*)d_in[2];
    const float* Wout = (const float*)d_in[3];
    const float* Wss  = (const float*)d_in[4];
    const float* Wvv0 = (const float*)d_in[5];
    const float* Wsv  = (const float*)d_in[6];
    const float* Wvs  = (const float*)d_in[7];
    const float* gmw  = (const float*)d_in[8];
    const float* gmb  = (const float*)d_in[9];
    const float* Wuss = (const float*)d_in[10];
    const float* Wuvv = (const float*)d_in[11];
    const float* Wusv = (const float*)d_in[12];
    const float* Wuvs = (const float*)d_in[13];
    const float* guw  = (const float*)d_in[14];
    const float* gub  = (const float*)d_in[15];
    const int*   eidx = (const int*)d_in[16];
    float* out = (float*)d_out;

    void *p_nv = 0, *p_as = 0, *p_av = 0;
    cudaGetSymbolAddress(&p_nv, g_nv);
    cudaGetSymbolAddress(&p_as, g_as);
    cudaGetSymbolAddress(&p_av, g_av);

    cudaFuncSetAttribute(k_bilin, cudaFuncAttributeMaxDynamicSharedMemorySize, BILIN_SMEM);

    cudaMemsetAsync(p_nv, 0, sizeof(float) * NN * 96, 0);
    k_in<<<NN / 32, 256>>>(x, Win);

    for (int l = 0; l < 2; l++) {
        k_feat<<<NN / 8, 256>>>(Wss + l * 4096, Wvv0 + l * 2048,
                                Wsv + l * 2048, Wvs + l * 1024);
        cudaMemsetAsync(p_as, 0, sizeof(float) * NN * 64, 0);
        cudaMemsetAsync(p_av, 0, sizeof(float) * NN * 96, 0);
        k_edge<<<EE / 8, 256>>>(eattr, eidx, gmw + l * 96, gmb + l * 96);
        k_bilin<<<NN / 64, 256, BILIN_SMEM>>>(Wuss + (size_t)l * 262144,
                                              Wuvv + (size_t)l * 65536,
                                              Wusv + (size_t)l * 65536,
                                              Wuvs + (size_t)l * 65536,
                                              guw + l * 96, gub + l * 96);
    }
    k_out<<<NN / 16, 256>>>(Wout, out);
}

// round 16
// speedup vs baseline: 2.0639x; 2.0639x over previous
#include <cuda_runtime.h>
#include <cuda_bf16.h>
#include <math.h>
#include <stdint.h>

#define NN 32768
#define EE 1048576
#define INV8 0.125f
#define C1 0.10206207261596575f
#define INV_R2 0.7071067811865476f
#define INVS32 0.17677669529663687f
#define S_USS 0.011048543456039806f
#define S_UVV 0.012757998811063534f
#define S_V 0.015625f
typedef unsigned long long ull;

__device__ float g_ns[NN * 64];
__device__ float g_nv[NN * 96];
__device__ float g_NF[(size_t)NN * 384];
__device__ float g_as[NN * 64];
__device__ float g_av[NN * 96];
// fragment-ordered bf16 weights (hi/lo split), built by k_prep
__device__ uint32_t g_W1h[458752], g_W1l[458752];   // [2][448 c][8 nb][32 lane][2 reg]
__device__ uint32_t g_W2h[131072], g_W2l[131072];   // [2][256 c][4 nb][32 lane][2 reg]

__device__ __forceinline__ float sigmf(float x) { return 1.0f / (1.0f + __expf(-x)); }
__device__ __forceinline__ ull pack2(float x, float y) {
    ull r;
    asm("mov.b64 %0, {%1, %2};" : "=l"(r) : "r"(__float_as_uint(x)), "r"(__float_as_uint(y)));
    return r;
}
__device__ __forceinline__ float2 unpack2(ull v) {
    unsigned int lo, hi;
    asm("mov.b64 {%0, %1}, %2;" : "=r"(lo), "=r"(hi) : "l"(v));
    return make_float2(__uint_as_float(lo), __uint_as_float(hi));
}
__device__ __forceinline__ ull fmul2(ull a, ull b) {
    ull r; asm("mul.rn.f32x2 %0, %1, %2;" : "=l"(r) : "l"(a), "l"(b)); return r;
}
// split packed f32 pair -> bf16x2 hi + bf16x2 lo (residual)
__device__ __forceinline__ void bsplit2(ull p, uint32_t& h, uint32_t& l) {
    float2 f = unpack2(p);
    asm("cvt.rn.bf16x2.f32 %0, %1, %2;" : "=r"(h) : "f"(f.y), "f"(f.x));
    float r0 = f.x - __uint_as_float(h << 16);
    float r1 = f.y - __uint_as_float(h & 0xffff0000u);
    asm("cvt.rn.bf16x2.f32 %0, %1, %2;" : "=r"(l) : "f"(r1), "f"(r0));
}
__device__ __forceinline__ void mma_bf16(float* d, const uint32_t* a, uint32_t b0, uint32_t b1) {
    asm volatile("mma.sync.aligned.m16n8k16.row.col.f32.bf16.bf16.f32 "
        "{%0,%1,%2,%3}, {%4,%5,%6,%7}, {%8,%9}, {%0,%1,%2,%3};"
        : "+f"(d[0]), "+f"(d[1]), "+f"(d[2]), "+f"(d[3])
        : "r"(a[0]), "r"(a[1]), "r"(a[2]), "r"(a[3]), "r"(b0), "r"(b1));
}

// ================= k_in =================
__global__ __launch_bounds__(256) void k_in(const float* __restrict__ x, const float* __restrict__ Win) {
    __shared__ float xs[32 * 65], ws[64 * 64];
    const int tid = threadIdx.x, node0 = blockIdx.x * 32;
    const float4* wg = (const float4*)Win;
    float4* w4 = (float4*)ws;
#pragma unroll
    for (int r = 0; r < 4; r++) w4[tid + r * 256] = wg[tid + r * 256];
#pragma unroll
    for (int r = 0; r < 8; r++) {
        int lin = tid + r * 256, t = lin >> 6, i = lin & 63;
        xs[t * 65 + i] = x[(size_t)(node0 + t) * 64 + i];
    }
    __syncthreads();
    const int o = tid & 63, tq = tid >> 6;
    float acc[8] = {0, 0, 0, 0, 0, 0, 0, 0};
#pragma unroll 16
    for (int i = 0; i < 64; i++) {
        float w = ws[i * 64 + o];
#pragma unroll
        for (int tt = 0; tt < 8; tt++) acc[tt] += xs[(tq * 8 + tt) * 65 + i] * w;
    }
#pragma unroll
    for (int tt = 0; tt < 8; tt++) g_ns[(size_t)(node0 + tq * 8 + tt) * 64 + o] = acc[tt] * INV8;
}

// ================= k_feat =================
__global__ __launch_bounds__(256) void k_feat(const float* __restrict__ Wss, const float* __restrict__ Wvv0,
                                              const float* __restrict__ Wsv, const float* __restrict__ Wvs) {
    __shared__ float s_wss[4096], s_wvv[2048], s_wsv[2048], s_wvs[1024], s_ns[8][64], s_nv[8][96];
    const int tid = threadIdx.x;
    for (int i = tid; i < 4096; i += 256) s_wss[i] = Wss[i];
    for (int i = tid; i < 2048; i += 256) s_wvv[i] = Wvv0[i];
    for (int i = tid; i < 2048; i += 256) s_wsv[i] = Wsv[i];
    for (int i = tid; i < 1024; i += 256) s_wvs[i] = Wvs[i];
    const int w = tid >> 5, lane = tid & 31, node = blockIdx.x * 8 + w;
#pragma unroll
    for (int r = 0; r < 2; r++) s_ns[w][lane + 32 * r] = g_ns[(size_t)node * 64 + lane + 32 * r];
#pragma unroll
    for (int r = 0; r < 3; r++) s_nv[w][lane + 32 * r] = g_nv[(size_t)node * 96 + lane + 32 * r];
    __syncthreads();
    float* nf = g_NF + (size_t)node * 384;
#pragma unroll
    for (int h = 0; h < 2; h++) {
        int o = lane + 32 * h; float a = 0;
#pragma unroll 8
        for (int i = 0; i < 64; i++) a += s_ns[w][i] * s_wss[i * 64 + o];
        nf[o] = a;
    }
#pragma unroll
    for (int xx = 0; xx < 3; xx++)
#pragma unroll
        for (int h = 0; h < 2; h++) {
            int o = lane + 32 * h; float a = 0;
#pragma unroll 8
            for (int m = 0; m < 32; m++) a += s_nv[w][m * 3 + xx] * s_wvv[m * 64 + o];
            nf[64 + xx * 64 + o] = a;
        }
    { float a = 0;
#pragma unroll 8
      for (int i = 0; i < 64; i++) a += s_ns[w][i] * s_wsv[i * 32 + lane];
      nf[256 + lane] = a; }
#pragma unroll
    for (int xx = 0; xx < 3; xx++) {
        float a = 0;
#pragma unroll 8
        for (int m = 0; m < 32; m++) a += s_nv[w][m * 3 + xx] * s_wvs[m * 32 + lane];
        nf[288 + xx * 32 + lane] = a;
    }
}

// ================= k_edge =================
__global__ __launch_bounds__(256) void k_edge(const float* __restrict__ eattr, const int* __restrict__ eidx,
                                              const float* __restrict__ gmw, const float* __restrict__ gmb) {
    __shared__ float s_gw[96], s_gb[96];
    const int tid = threadIdx.x;
    if (tid < 96) { s_gw[tid] = gmw[tid]; s_gb[tid] = gmb[tid]; }
    __syncthreads();
    const int w = tid >> 5, lane = tid & 31, e = blockIdx.x * 8 + w;
    const int r = eidx[e], c = eidx[EE + e];
    const float ev0 = eattr[(size_t)e * 4], ev1 = eattr[(size_t)e * 4 + 1];
    const float ev2 = eattr[(size_t)e * 4 + 2], es = eattr[(size_t)e * 4 + 3];
    const float* nf = g_NF + (size_t)c * 384;
    float ms[2];
#pragma unroll
    for (int h = 0; h < 2; h++) {
        int o = lane + 32 * h;
        float dot = ev0 * nf[64 + o] + ev1 * nf[128 + o] + ev2 * nf[192 + o];
        float v = (es * nf[o] * INV8 + dot * C1) * INV_R2;
        ms[h] = v * sigmf(v);
    }
    const float sv = nf[256 + lane];
    float mv0 = (sv * ev0 * INV8 + es * nf[288 + lane] * INVS32) * INV_R2;
    float mv1 = (sv * ev1 * INV8 + es * nf[320 + lane] * INVS32) * INV_R2;
    float mv2 = (sv * ev2 * INV8 + es * nf[352 + lane] * INVS32) * INV_R2;
    float p = mv0 + mv1 + mv2;
#pragma unroll
    for (int off = 16; off; off >>= 1) p += __shfl_xor_sync(0xffffffffu, p, off);
    const float mean = p * (1.0f / 96.0f);
    const float g0 = sigmf(mean * s_gw[lane * 3] + s_gb[lane * 3]);
    const float g1 = sigmf(mean * s_gw[lane * 3 + 1] + s_gb[lane * 3 + 1]);
    const float g2 = sigmf(mean * s_gw[lane * 3 + 2] + s_gb[lane * 3 + 2]);
    float* as = g_as + (size_t)r * 64;
    float* av = g_av + (size_t)r * 96;
    atomicAdd(as + lane, ms[0]);
    atomicAdd(as + lane + 32, ms[1]);
    atomicAdd(av + lane * 3, mv0 * g0);
    atomicAdd(av + lane * 3 + 1, mv1 * g1);
    atomicAdd(av + lane * 3 + 2, mv2 * g2);
}

// ====== k_prep: scale + bf16 hi/lo split + mma-fragment-order the bilinear weights ======
__global__ __launch_bounds__(256) void k_prep(const float* __restrict__ Wuss, const float* __restrict__ Wuvv,
                                              const float* __restrict__ Wusv, const float* __restrict__ Wuvs) {
    int idx = blockIdx.x * 256 + threadIdx.x;   // 0 .. 589823
    float w0, w1; uint32_t *H, *Lo; int dst;
    if (idx < 458752) {                         // GEMM1: D1[.,64], K=7168
        int l = idx / 229376, rem = idx % 229376;
        int c = rem / 512, rem2 = rem % 512;
        int q = rem2 & 63, lane = q >> 1, reg = q & 1;
        int nb = rem2 >> 6;
        int n = nb * 8 + (lane >> 2);
        int k0 = c * 16 + (lane & 3) * 2 + reg * 8;
        if (k0 < 4096) {                        // uss: W[k][n]
            const float* b = Wuss + (size_t)l * 262144;
            w0 = b[(size_t)k0 * 64 + n] * S_USS;
            w1 = b[(size_t)(k0 + 1) * 64 + n] * S_USS;
        } else {                                // uvv: k'=(x<<10)|(m<<5)|nn -> W[(m*32+nn)][n]
            int kp = k0 - 4096, km = kp & 1023, m = km >> 5, nn = km & 31;
            const float* b = Wuvv + (size_t)l * 65536;
            w0 = b[(m * 32 + nn) * 64 + n] * S_UVV;
            w1 = b[(m * 32 + nn + 1) * 64 + n] * S_UVV;
        }
        H = g_W1h; Lo = g_W1l; dst = idx;
    } else {                                    // GEMM2: D2[.,32], K=4096
        int j = idx - 458752;
        int l = j / 65536, rem = j % 65536;
        int c = rem / 256, rem2 = rem % 256;
        int q = rem2 & 63, lane = q >> 1, reg = q & 1;
        int nb = rem2 >> 6;
        int n = nb * 8 + (lane >> 2);
        int k0 = c * 16 + (lane & 3) * 2 + reg * 8;
        if (k0 < 2048) {                        // usv: W[k][n]
            const float* b = Wusv + (size_t)l * 65536;
            w0 = b[(size_t)k0 * 32 + n] * S_V;
            w1 = b[(size_t)(k0 + 1) * 32 + n] * S_V;
        } else {                                // uvs
            const float* b = Wuvs + (size_t)l * 65536;
            w0 = b[(size_t)(k0 - 2048) * 32 + n] * S_V;
            w1 = b[(size_t)(k0 - 2047) * 32 + n] * S_V;
        }
        H = g_W2h; Lo = g_W2l; dst = j;
    }
    uint32_t h, lo;
    bsplit2(pack2(w0, w1), h, lo);
    H[dst] = h; Lo[dst] = lo;
}

// ====== k_bilin_mma: HMMA bf16-x3, 64 nodes/block, 8 warps, 2 blocks/SM ======
// smem floats: ns 64x66 | as 64x66 | nv 64x96 | av 64x100 ([x*32+n]) | red 256
#define SM_AS 4224
#define SM_NV 8448
#define SM_AV 14592
#define SM_RED 20992
#define MMA_SMEM (21248 * 4)

__global__ __launch_bounds__(256, 2) void k_bilin_mma(int L, const float* __restrict__ guw,
                                                      const float* __restrict__ gub) {
    extern __shared__ float sm[];
    float* ns_s = sm;
    float* as_s = sm + SM_AS;
    float* nv_s = sm + SM_NV;
    float* av_s = sm + SM_AV;
    float* red  = sm + SM_RED;
    const int tid = threadIdx.x, lane = tid & 31, w = tid >> 5;
    const int rg = w & 1, cg = w >> 1;               // warp tile: rows rg*32, cols cg*16 (G1) / cg*8 (G2)
    const int g = lane >> 2, cl = (lane & 3) * 2;
    const int node0 = blockIdx.x * 64;
    int R[4];
#pragma unroll
    for (int j = 0; j < 4; j++) R[j] = rg * 32 + j * 8 + g;

    {   // feature load (av reordered to [x*32+n])
        const float4* gns = (const float4*)(g_ns + (size_t)node0 * 64);
        const float4* gas = (const float4*)(g_as + (size_t)node0 * 64);
#pragma unroll
        for (int r = 0; r < 4; r++) {
            int lin = tid + r * 256, t = lin >> 4, c = (lin & 15) * 4;
            float4 v = gns[lin], u = gas[lin];
            float* p = ns_s + t * 66 + c; p[0] = v.x; p[1] = v.y; p[2] = v.z; p[3] = v.w;
            float* q = as_s + t * 66 + c; q[0] = u.x; q[1] = u.y; q[2] = u.z; q[3] = u.w;
        }
        const float4* gnv = (const float4*)(g_nv + (size_t)node0 * 96);
        const float4* gav = (const float4*)(g_av + (size_t)node0 * 96);
#pragma unroll
        for (int r = 0; r < 6; r++) {
            int lin = tid + r * 256, t = lin / 24, c4 = lin % 24;
            float4 v = gnv[lin], u = gav[lin];
            float vv[4] = {v.x, v.y, v.z, v.w}, uu[4] = {u.x, u.y, u.z, u.w};
#pragma unroll
            for (int q = 0; q < 4; q++) {
                int f = c4 * 4 + q, n = f / 3, x = f - n * 3;
                nv_s[t * 96 + f] = vv[q];
                av_s[t * 100 + x * 32 + n] = uu[q];
            }
        }
    }
    __syncthreads();

    const ull* W1h = (const ull*)g_W1h;
    const ull* W1l = (const ull*)g_W1l;

    // ---------------- GEMM1: D1[64,64] = A1[64,7168] * W1 ----------------
    float d1[16];
#pragma unroll
    for (int q = 0; q < 16; q++) d1[q] = 0.f;

#define G1_MMA() do { \
        size_t wb = ((size_t)(L * 448 + c) * 8 + cg * 2) * 32 + lane; \
        ull h0 = __ldg(W1h + wb), h1 = __ldg(W1h + wb + 32); \
        ull l0 = __ldg(W1l + wb), l1 = __ldg(W1l + wb + 32); \
        _Pragma("unroll") for (int m = 0; m < 2; m++) { \
            mma_bf16(d1 + (m * 2) * 4,     ah[m], (uint32_t)h0, (uint32_t)(h0 >> 32)); \
            mma_bf16(d1 + (m * 2) * 4,     ah[m], (uint32_t)l0, (uint32_t)(l0 >> 32)); \
            mma_bf16(d1 + (m * 2) * 4,     al[m], (uint32_t)h0, (uint32_t)(h0 >> 32)); \
            mma_bf16(d1 + (m * 2 + 1) * 4, ah[m], (uint32_t)h1, (uint32_t)(h1 >> 32)); \
            mma_bf16(d1 + (m * 2 + 1) * 4, ah[m], (uint32_t)l1, (uint32_t)(l1 >> 32)); \
            mma_bf16(d1 + (m * 2 + 1) * 4, al[m], (uint32_t)h1, (uint32_t)(h1 >> 32)); \
        } } while (0)

#pragma unroll 1
    for (int c = 0; c < 256; c++) {                  // uss: i=c>>2, j0=(c&3)*16
        const int i = c >> 2, j0 = (c & 3) * 16;
        uint32_t ah[2][4], al[2][4];
#pragma unroll
        for (int j = 0; j < 4; j++) {
            float u = ns_s[R[j] * 66 + i];
            ull u2 = pack2(u, u);
            const float* vp = as_s + R[j] * 66 + j0;
            ull pa = fmul2(u2, *(const ull*)(vp + cl));
            ull pb = fmul2(u2, *(const ull*)(vp + cl + 8));
            int m = j >> 1, s = j & 1;
            bsplit2(pa, ah[m][s], al[m][s]);
            bsplit2(pb, ah[m][s + 2], al[m][s + 2]);
        }
        G1_MMA();
    }
#pragma unroll 1
    for (int c = 256; c < 448; c++) {                // uvv: x=cc>>6, m2=(cc&63)>>1, n0=(cc&1)*16
        const int cc = c - 256, x = cc >> 6, m2 = (cc & 63) >> 1, n0 = (cc & 1) * 16;
        uint32_t ah[2][4], al[2][4];
#pragma unroll
        for (int j = 0; j < 4; j++) {
            float u = nv_s[R[j] * 96 + m2 * 3 + x];
            ull u2 = pack2(u, u);
            const float* vp = av_s + R[j] * 100 + x * 32 + n0;
            ull pa = fmul2(u2, *(const ull*)(vp + cl));
            ull pb = fmul2(u2, *(const ull*)(vp + cl + 8));
            int m = j >> 1, s = j & 1;
            bsplit2(pa, ah[m][s], al[m][s]);
            bsplit2(pb, ah[m][s + 2], al[m][s + 2]);
        }
        G1_MMA();
    }
    // u_s epilogue: silu + residual
#pragma unroll
    for (int m = 0; m < 2; m++)
#pragma unroll
        for (int nb = 0; nb < 2; nb++)
#pragma unroll
            for (int h = 0; h < 2; h++) {
                int row = rg * 32 + m * 16 + h * 8 + g;
                int col = cg * 16 + nb * 8 + cl;
                float v0 = d1[(m * 2 + nb) * 4 + h * 2], v1 = d1[(m * 2 + nb) * 4 + h * 2 + 1];
                float2 o;
                o.x = ns_s[row * 66 + col] + v0 * sigmf(v0);
                o.y = ns_s[row * 66 + col + 1] + v1 * sigmf(v1);
                *(float2*)(g_ns + (size_t)(node0 + row) * 64 + col) = o;
            }

    // ---------------- GEMM2: D2x[64,32] = A2x[64,4096] * W2, x=0..2 ----------------
    const ull* W2h = (const ull*)g_W2h;
    const ull* W2l = (const ull*)g_W2l;
    float d2[24];
#pragma unroll
    for (int q = 0; q < 24; q++) d2[q] = 0.f;

#pragma unroll 1
    for (int c = 0; c < 128; c++) {                  // usv: i=c>>1, n0=(c&1)*16 (u shared over x)
        size_t wb = ((size_t)(L * 256 + c) * 4 + cg) * 32 + lane;
        ull h0 = __ldg(W2h + wb), l0 = __ldg(W2l + wb);
        const int i = c >> 1, n0 = (c & 1) * 16;
        ull u2[4];
#pragma unroll
        for (int j = 0; j < 4; j++) {
            float u = ns_s[R[j] * 66 + i];
            u2[j] = pack2(u, u);
        }
#pragma unroll
        for (int x = 0; x < 3; x++) {
            uint32_t ah[2][4], al[2][4];
#pragma unroll
            for (int j = 0; j < 4; j++) {
                const float* vp = av_s + R[j] * 100 + x * 32 + n0;
                ull pa = fmul2(u2[j], *(const ull*)(vp + cl));
                ull pb = fmul2(u2[j], *(const ull*)(vp + cl + 8));
                int m = j >> 1, s = j & 1;
                bsplit2(pa, ah[m][s], al[m][s]);
                bsplit2(pb, ah[m][s + 2], al[m][s + 2]);
            }
#pragma unroll
            for (int m = 0; m < 2; m++) {
                float* dd = d2 + (x * 2 + m) * 4;
                mma_bf16(dd, ah[m], (uint32_t)h0, (uint32_t)(h0 >> 32));
                mma_bf16(dd, ah[m], (uint32_t)l0, (uint32_t)(l0 >> 32));
                mma_bf16(dd, al[m], (uint32_t)h0, (uint32_t)(h0 >> 32));
            }
        }
    }
#pragma unroll 1
    for (int c = 128; c < 256; c++) {                // uvs: m2=cc>>2, j0=(cc&3)*16 (v shared over x)
        size_t wb = ((size_t)(L * 256 + c) * 4 + cg) * 32 + lane;
        ull h0 = __ldg(W2h + wb), l0 = __ldg(W2l + wb);
        const int cc = c - 128, m2 = cc >> 2, j0 = (cc & 3) * 16;
        ull va[4], vb[4];
#pragma unroll
        for (int j = 0; j < 4; j++) {
            const float* vp = as_s + R[j] * 66 + j0;
            va[j] = *(const ull*)(vp + cl);
            vb[j] = *(const ull*)(vp + cl + 8);
        }
#pragma unroll
        for (int x = 0; x < 3; x++) {
            uint32_t ah[2][4], al[2][4];
#pragma unroll
            for (int j = 0; j < 4; j++) {
                float u = nv_s[R[j] * 96 + m2 * 3 + x];
                ull u2v = pack2(u, u);
                ull pa = fmul2(u2v, va[j]);
                ull pb = fmul2(u2v, vb[j]);
                int m = j >> 1, s = j & 1;
                bsplit2(pa, ah[m][s], al[m][s]);
                bsplit2(pb, ah[m][s + 2], al[m][s + 2]);
            }
#pragma unroll
            for (int m = 0; m < 2; m++) {
                float* dd = d2 + (x * 2 + m) * 4;
                mma_bf16(dd, ah[m], (uint32_t)h0, (uint32_t)(h0 >> 32));
                mma_bf16(dd, ah[m], (uint32_t)l0, (uint32_t)(l0 >> 32));
                mma_bf16(dd, al[m], (uint32_t)h0, (uint32_t)(h0 >> 32));
            }
        }
    }

    // ---- gate mean over 96 per node: in-warp col reduce, cross-warp via smem ----
    {
        float rs[4];
#pragma unroll
        for (int m = 0; m < 2; m++)
#pragma unroll
            for (int h = 0; h < 2; h++) {
                float s = 0.f;
#pragma unroll
                for (int x = 0; x < 3; x++)
                    s += d2[(x * 2 + m) * 4 + h * 2] + d2[(x * 2 + m) * 4 + h * 2 + 1];
                rs[m * 2 + h] = s;
            }
#pragma unroll
        for (int q = 0; q < 4; q++) {
            rs[q] += __shfl_xor_sync(0xffffffffu, rs[q], 1);
            rs[q] += __shfl_xor_sync(0xffffffffu, rs[q], 2);
        }
        if ((lane & 3) == 0) {
#pragma unroll
            for (int m = 0; m < 2; m++)
#pragma unroll
                for (int h = 0; h < 2; h++)
                    red[cg * 64 + rg * 32 + m * 16 + h * 8 + g] = rs[m * 2 + h];
        }
        __syncthreads();
#pragma unroll
        for (int m = 0; m < 2; m++)
#pragma unroll
            for (int h = 0; h < 2; h++) {
                int row = rg * 32 + m * 16 + h * 8 + g;
                float mean = (red[row] + red[64 + row] + red[128 + row] + red[192 + row]) * (1.0f / 96.0f);
#pragma unroll
                for (int x = 0; x < 3; x++)
#pragma unroll
                    for (int q2 = 0; q2 < 2; q2++) {
                        int o = cg * 8 + cl + q2, f = o * 3 + x;
                        float v = d2[(x * 2 + m) * 4 + h * 2 + q2];
                        float gt = sigmf(mean * __ldg(guw + f) + __ldg(gub + f));
                        g_nv[(size_t)(node0 + row) * 96 + f] = nv_s[row * 96 + f] + v * gt;
                    }
            }
    }
}

// ================= k_out =================
__global__ __launch_bounds__(256) void k_out(const float* __restrict__ Wout, float* __restrict__ out) {
    __shared__ float s_w[32 * 256], s_ns[16 * 64];
    const int tid = threadIdx.x, node0 = blockIdx.x * 16;
#pragma unroll
    for (int r = 0; r < 4; r++) {
        int lin = tid + r * 256, t = lin >> 6, i = lin & 63;
        s_ns[t * 64 + i] = g_ns[(size_t)(node0 + t) * 64 + i];
    }
    float acc[16];
#pragma unroll
    for (int t = 0; t < 16; t++) acc[t] = 0.f;
    for (int ic = 0; ic < 2; ic++) {
        __syncthreads();
        const float4* wg = (const float4*)(Wout + (size_t)ic * 8192);
        float4* w4 = (float4*)s_w;
#pragma unroll
        for (int r = 0; r < 8; r++) w4[tid + r * 256] = wg[tid + r * 256];
        __syncthreads();
#pragma unroll 8
        for (int i = 0; i < 32; i++) {
            float w = s_w[i * 256 + tid];
#pragma unroll
            for (int t = 0; t < 16; t++) acc[t] += s_ns[t * 64 + ic * 32 + i] * w;
        }
    }
#pragma unroll
    for (int t = 0; t < 16; t++) out[(size_t)(node0 + t) * 256 + tid] = acc[t] * INV8;
}

extern "C" void kernel_launch(void* const* d_in, const int* in_sizes, int n_in,
                              void* d_out, int out_size) {
    const float* x    = (const float*)d_in[0];
    const float* eattr= (const float*)d_in[1];
    const float* Win  = (const float*)d_in[2];
    const float* Wout = (const float*)d_in[3];
    const float* Wss  = (const float*)d_in[4];
    const float* Wvv0 = (const float*)d_in[5];
    const float* Wsv  = (const float*)d_in[6];
    const float* Wvs  = (const float*)d_in[7];
    const float* gmw  = (const float*)d_in[8];
    const float* gmb  = (const float*)d_in[9];
    const float* Wuss = (const float*)d_in[10];
    const float* Wuvv = (const float*)d_in[11];
    const float* Wusv = (const float*)d_in[12];
    const float* Wuvs = (const float*)d_in[13];
    const float* guw  = (const float*)d_in[14];
    const float* gub  = (const float*)d_in[15];
    const int*   eidx = (const int*)d_in[16];
    float* out = (float*)d_out;

    void *p_nv = 0, *p_as = 0, *p_av = 0;
    cudaGetSymbolAddress(&p_nv, g_nv);
    cudaGetSymbolAddress(&p_as, g_as);
    cudaGetSymbolAddress(&p_av, g_av);
    cudaFuncSetAttribute(k_bilin_mma, cudaFuncAttributeMaxDynamicSharedMemorySize, MMA_SMEM);

    cudaMemsetAsync(p_nv, 0, sizeof(float) * NN * 96, 0);
    k_prep<<<2304, 256>>>(Wuss, Wuvv, Wusv, Wuvs);
    k_in<<<NN / 32, 256>>>(x, Win);
    for (int l = 0; l < 2; l++) {
        k_feat<<<NN / 8, 256>>>(Wss + l * 4096, Wvv0 + l * 2048, Wsv + l * 2048, Wvs + l * 1024);
        cudaMemsetAsync(p_as, 0, sizeof(float) * NN * 64, 0);
        cudaMemsetAsync(p_av, 0, sizeof(float) * NN * 96, 0);
        k_edge<<<EE / 8, 256>>>(eattr, eidx, gmw + l * 96, gmb + l * 96);
        k_bilin_mma<<<NN / 64, 256, MMA_SMEM>>>(l, guw + l * 96, gub + l * 96);
    }
    k_out<<<NN / 16, 256>>>(Wout, out);
}

// round 17
// speedup vs baseline: 2.5592x; 1.2400x over previous
#include <cuda_runtime.h>
#include <cuda_bf16.h>
#include <math.h>
#include <stdint.h>

#define NN 32768
#define EE 1048576
#define INV8 0.125f
#define S_USS 0.011048543456039806f
#define S_UVV 0.012757998811063534f
#define S_V 0.015625f
// prescale factors folded into g_NF
#define P_SS 0.08838834764831845f   // INV8*INV_R2
#define P_Q  0.07216878364870323f   // C1*INV_R2
#define P_SV 0.08838834764831845f   // INV8*INV_R2
#define P_VS 0.125f                 // INVS32*INV_R2
typedef unsigned long long ull;

__device__ float g_ns[NN * 64];
__device__ float g_nv[NN * 96];
__device__ float g_NF[(size_t)NN * 384];
__device__ float g_as[NN * 64];
__device__ float g_av[NN * 96];
__device__ uint32_t g_W1h[458752], g_W1l[458752];   // [2][448 c][8 nb][32 lane][2 reg]
__device__ uint32_t g_W2h[131072], g_W2l[131072];   // [2][256 c][4 nb][32 lane][2 reg]

__device__ __forceinline__ float sigmf(float x) { return 1.0f / (1.0f + __expf(-x)); }
__device__ __forceinline__ ull pack2(float x, float y) {
    ull r;
    asm("mov.b64 %0, {%1, %2};" : "=l"(r) : "r"(__float_as_uint(x)), "r"(__float_as_uint(y)));
    return r;
}
__device__ __forceinline__ float2 unpack2(ull v) {
    unsigned int lo, hi;
    asm("mov.b64 {%0, %1}, %2;" : "=r"(lo), "=r"(hi) : "l"(v));
    return make_float2(__uint_as_float(lo), __uint_as_float(hi));
}
__device__ __forceinline__ ull fmul2(ull a, ull b) {
    ull r; asm("mul.rn.f32x2 %0, %1, %2;" : "=l"(r) : "l"(a), "l"(b)); return r;
}
__device__ __forceinline__ void bsplit2(ull p, uint32_t& h, uint32_t& l) {
    float2 f = unpack2(p);
    asm("cvt.rn.bf16x2.f32 %0, %1, %2;" : "=r"(h) : "f"(f.y), "f"(f.x));
    float r0 = f.x - __uint_as_float(h << 16);
    float r1 = f.y - __uint_as_float(h & 0xffff0000u);
    asm("cvt.rn.bf16x2.f32 %0, %1, %2;" : "=r"(l) : "f"(r1), "f"(r0));
}
__device__ __forceinline__ void mma_bf16(float* d, const uint32_t* a, uint32_t b0, uint32_t b1) {
    asm volatile("mma.sync.aligned.m16n8k16.row.col.f32.bf16.bf16.f32 "
        "{%0,%1,%2,%3}, {%4,%5,%6,%7}, {%8,%9}, {%0,%1,%2,%3};"
        : "+f"(d[0]), "+f"(d[1]), "+f"(d[2]), "+f"(d[3])
        : "r"(a[0]), "r"(a[1]), "r"(a[2]), "r"(a[3]), "r"(b0), "r"(b1));
}

// ================= k_in =================
__global__ __launch_bounds__(256) void k_in(const float* __restrict__ x, const float* __restrict__ Win) {
    __shared__ float xs[32 * 65], ws[64 * 64];
    const int tid = threadIdx.x, node0 = blockIdx.x * 32;
    const float4* wg = (const float4*)Win;
    float4* w4 = (float4*)ws;
#pragma unroll
    for (int r = 0; r < 4; r++) w4[tid + r * 256] = wg[tid + r * 256];
#pragma unroll
    for (int r = 0; r < 8; r++) {
        int lin = tid + r * 256, t = lin >> 6, i = lin & 63;
        xs[t * 65 + i] = x[(size_t)(node0 + t) * 64 + i];
    }
    __syncthreads();
    const int o = tid & 63, tq = tid >> 6;
    float acc[8] = {0, 0, 0, 0, 0, 0, 0, 0};
#pragma unroll 16
    for (int i = 0; i < 64; i++) {
        float w = ws[i * 64 + o];
#pragma unroll
        for (int tt = 0; tt < 8; tt++) acc[tt] += xs[(tq * 8 + tt) * 65 + i] * w;
    }
#pragma unroll
    for (int tt = 0; tt < 8; tt++) g_ns[(size_t)(node0 + tq * 8 + tt) * 64 + o] = acc[tt] * INV8;
}

// ================= k_feat (stores PRESCALED features) =================
__global__ __launch_bounds__(256) void k_feat(const float* __restrict__ Wss, const float* __restrict__ Wvv0,
                                              const float* __restrict__ Wsv, const float* __restrict__ Wvs) {
    __shared__ float s_wss[4096], s_wvv[2048], s_wsv[2048], s_wvs[1024], s_ns[8][64], s_nv[8][96];
    const int tid = threadIdx.x;
    for (int i = tid; i < 4096; i += 256) s_wss[i] = Wss[i];
    for (int i = tid; i < 2048; i += 256) s_wvv[i] = Wvv0[i];
    for (int i = tid; i < 2048; i += 256) s_wsv[i] = Wsv[i];
    for (int i = tid; i < 1024; i += 256) s_wvs[i] = Wvs[i];
    const int w = tid >> 5, lane = tid & 31, node = blockIdx.x * 8 + w;
#pragma unroll
    for (int r = 0; r < 2; r++) s_ns[w][lane + 32 * r] = g_ns[(size_t)node * 64 + lane + 32 * r];
#pragma unroll
    for (int r = 0; r < 3; r++) s_nv[w][lane + 32 * r] = g_nv[(size_t)node * 96 + lane + 32 * r];
    __syncthreads();
    float* nf = g_NF + (size_t)node * 384;
#pragma unroll
    for (int h = 0; h < 2; h++) {
        int o = lane + 32 * h; float a = 0;
#pragma unroll 8
        for (int i = 0; i < 64; i++) a += s_ns[w][i] * s_wss[i * 64 + o];
        nf[o] = a * P_SS;
    }
#pragma unroll
    for (int xx = 0; xx < 3; xx++)
#pragma unroll
        for (int h = 0; h < 2; h++) {
            int o = lane + 32 * h; float a = 0;
#pragma unroll 8
            for (int m = 0; m < 32; m++) a += s_nv[w][m * 3 + xx] * s_wvv[m * 64 + o];
            nf[64 + xx * 64 + o] = a * P_Q;
        }
    { float a = 0;
#pragma unroll 8
      for (int i = 0; i < 64; i++) a += s_ns[w][i] * s_wsv[i * 32 + lane];
      nf[256 + lane] = a * P_SV; }
#pragma unroll
    for (int xx = 0; xx < 3; xx++) {
        float a = 0;
#pragma unroll 8
        for (int m = 0; m < 32; m++) a += s_nv[w][m * 3 + xx] * s_wvs[m * 32 + lane];
        nf[288 + xx * 32 + lane] = a * P_VS;
    }
}

// ================= k_edge (prescaled NF) =================
__global__ __launch_bounds__(256) void k_edge(const float* __restrict__ eattr, const int* __restrict__ eidx,
                                              const float* __restrict__ gmw, const float* __restrict__ gmb) {
    __shared__ float s_gw[96], s_gb[96];
    const int tid = threadIdx.x;
    if (tid < 96) { s_gw[tid] = gmw[tid]; s_gb[tid] = gmb[tid]; }
    __syncthreads();
    const int w = tid >> 5, lane = tid & 31, e = blockIdx.x * 8 + w;
    const int r = eidx[e], c = eidx[EE + e];
    const float ev0 = eattr[(size_t)e * 4], ev1 = eattr[(size_t)e * 4 + 1];
    const float ev2 = eattr[(size_t)e * 4 + 2], es = eattr[(size_t)e * 4 + 3];
    const float* nf = g_NF + (size_t)c * 384;
    float ms[2];
#pragma unroll
    for (int h = 0; h < 2; h++) {
        int o = lane + 32 * h;
        float v = es * nf[o] + ev0 * nf[64 + o] + ev1 * nf[128 + o] + ev2 * nf[192 + o];
        ms[h] = v * sigmf(v);
    }
    const float sv = nf[256 + lane];
    float mv0 = sv * ev0 + es * nf[288 + lane];
    float mv1 = sv * ev1 + es * nf[320 + lane];
    float mv2 = sv * ev2 + es * nf[352 + lane];
    float p = mv0 + mv1 + mv2;
#pragma unroll
    for (int off = 16; off; off >>= 1) p += __shfl_xor_sync(0xffffffffu, p, off);
    const float mean = p * (1.0f / 96.0f);
    const float g0 = sigmf(mean * s_gw[lane * 3] + s_gb[lane * 3]);
    const float g1 = sigmf(mean * s_gw[lane * 3 + 1] + s_gb[lane * 3 + 1]);
    const float g2 = sigmf(mean * s_gw[lane * 3 + 2] + s_gb[lane * 3 + 2]);
    float* as = g_as + (size_t)r * 64;
    float* av = g_av + (size_t)r * 96;
    atomicAdd(as + lane, ms[0]);
    atomicAdd(as + lane + 32, ms[1]);
    atomicAdd(av + lane * 3, mv0 * g0);
    atomicAdd(av + lane * 3 + 1, mv1 * g1);
    atomicAdd(av + lane * 3 + 2, mv2 * g2);
}

// ====== k_prep (unchanged fragment layout) ======
__global__ __launch_bounds__(256) void k_prep(const float* __restrict__ Wuss, const float* __restrict__ Wuvv,
                                              const float* __restrict__ Wusv, const float* __restrict__ Wuvs) {
    int idx = blockIdx.x * 256 + threadIdx.x;
    float w0, w1; uint32_t *H, *Lo; int dst;
    if (idx < 458752) {
        int l = idx / 229376, rem = idx % 229376;
        int c = rem / 512, rem2 = rem % 512;
        int q = rem2 & 63, lane = q >> 1, reg = q & 1;
        int nb = rem2 >> 6;
        int n = nb * 8 + (lane >> 2);
        int k0 = c * 16 + (lane & 3) * 2 + reg * 8;
        if (k0 < 4096) {
            const float* b = Wuss + (size_t)l * 262144;
            w0 = b[(size_t)k0 * 64 + n] * S_USS;
            w1 = b[(size_t)(k0 + 1) * 64 + n] * S_USS;
        } else {
            int kp = k0 - 4096, km = kp & 1023, m = km >> 5, nn = km & 31;
            const float* b = Wuvv + (size_t)l * 65536;
            w0 = b[(m * 32 + nn) * 64 + n] * S_UVV;
            w1 = b[(m * 32 + nn + 1) * 64 + n] * S_UVV;
        }
        H = g_W1h; Lo = g_W1l; dst = idx;
    } else {
        int j = idx - 458752;
        int l = j / 65536, rem = j % 65536;
        int c = rem / 256, rem2 = rem % 256;
        int q = rem2 & 63, lane = q >> 1, reg = q & 1;
        int nb = rem2 >> 6;
        int n = nb * 8 + (lane >> 2);
        int k0 = c * 16 + (lane & 3) * 2 + reg * 8;
        if (k0 < 2048) {
            const float* b = Wusv + (size_t)l * 65536;
            w0 = b[(size_t)k0 * 32 + n] * S_V;
            w1 = b[(size_t)(k0 + 1) * 32 + n] * S_V;
        } else {
            const float* b = Wuvs + (size_t)l * 65536;
            w0 = b[(size_t)(k0 - 2048) * 32 + n] * S_V;
            w1 = b[(size_t)(k0 - 2047) * 32 + n] * S_V;
        }
        H = g_W2h; Lo = g_W2l; dst = j;
    }
    uint32_t h, lo;
    bsplit2(pack2(w0, w1), h, lo);
    H[dst] = h; Lo[dst] = lo;
}

// ====== k_bilin_mma: HMMA bf16-x3, 64 nodes/block, warps = 4rg x 2cg ======
#define SM_AS 4224
#define SM_NV 8448
#define SM_AV 14592
#define SM_RED 20992
#define MMA_SMEM (21248 * 4)

__global__ __launch_bounds__(256, 2) void k_bilin_mma(int L, const float* __restrict__ guw,
                                                      const float* __restrict__ gub) {
    extern __shared__ float sm[];
    float* ns_s = sm;
    float* as_s = sm + SM_AS;
    float* nv_s = sm + SM_NV;
    float* av_s = sm + SM_AV;
    float* red  = sm + SM_RED;
    const int tid = threadIdx.x, lane = tid & 31, w = tid >> 5;
    const int rg = w & 3, cg = w >> 2;               // rows rg*16, cols cg*32 (G1) / cg*16 (G2)
    const int g = lane >> 2, cl = (lane & 3) * 2;
    const int node0 = blockIdx.x * 64;
    const int R0 = rg * 16 + g, R1 = rg * 16 + 8 + g;

    {   // feature load (av reordered to [x*32+n])
        const float4* gns = (const float4*)(g_ns + (size_t)node0 * 64);
        const float4* gas = (const float4*)(g_as + (size_t)node0 * 64);
#pragma unroll
        for (int r = 0; r < 4; r++) {
            int lin = tid + r * 256, t = lin >> 4, c = (lin & 15) * 4;
            float4 v = gns[lin], u = gas[lin];
            float* p = ns_s + t * 66 + c; p[0] = v.x; p[1] = v.y; p[2] = v.z; p[3] = v.w;
            float* q = as_s + t * 66 + c; q[0] = u.x; q[1] = u.y; q[2] = u.z; q[3] = u.w;
        }
        const float4* gnv = (const float4*)(g_nv + (size_t)node0 * 96);
        const float4* gav = (const float4*)(g_av + (size_t)node0 * 96);
#pragma unroll
        for (int r = 0; r < 6; r++) {
            int lin = tid + r * 256, t = lin / 24, c4 = lin % 24;
            float4 v = gnv[lin], u = gav[lin];
            float vv[4] = {v.x, v.y, v.z, v.w}, uu[4] = {u.x, u.y, u.z, u.w};
#pragma unroll
            for (int q = 0; q < 4; q++) {
                int f = c4 * 4 + q, n = f / 3, x = f - n * 3;
                nv_s[t * 96 + f] = vv[q];
                av_s[t * 100 + x * 32 + n] = uu[q];
            }
        }
    }
    __syncthreads();

    const ull* W1h = (const ull*)g_W1h;
    const ull* W1l = (const ull*)g_W1l;

    // ---------------- GEMM1: D1[64,64], warp tile 16r x 32c ----------------
    float d1[16];
#pragma unroll
    for (int q = 0; q < 16; q++) d1[q] = 0.f;

#pragma unroll 1
    for (int c = 0; c < 448; c++) {
        uint32_t ah[4], al[4];
#pragma unroll
        for (int j = 0; j < 2; j++) {
            const int row = j ? R1 : R0;
            float u; const float* vp;
            if (c < 256) {
                u = ns_s[row * 66 + (c >> 2)];
                vp = as_s + row * 66 + (c & 3) * 16;
            } else {
                const int cc = c - 256, x = cc >> 6;
                u = nv_s[row * 96 + ((cc & 63) >> 1) * 3 + x];
                vp = av_s + row * 100 + x * 32 + (cc & 1) * 16;
            }
            ull u2 = pack2(u, u);
            ull pa = fmul2(u2, *(const ull*)(vp + cl));
            ull pb = fmul2(u2, *(const ull*)(vp + cl + 8));
            bsplit2(pa, ah[j], al[j]);
            bsplit2(pb, ah[j + 2], al[j + 2]);
        }
        size_t wb = ((size_t)(L * 448 + c) * 8 + cg * 4) * 32 + lane;
#pragma unroll
        for (int nb = 0; nb < 4; nb++) {
            ull h = __ldg(W1h + wb + nb * 32), l = __ldg(W1l + wb + nb * 32);
            float* dd = d1 + nb * 4;
            mma_bf16(dd, ah, (uint32_t)h, (uint32_t)(h >> 32));
            mma_bf16(dd, ah, (uint32_t)l, (uint32_t)(l >> 32));
            mma_bf16(dd, al, (uint32_t)h, (uint32_t)(h >> 32));
        }
    }
    // u_s epilogue
#pragma unroll
    for (int nb = 0; nb < 4; nb++)
#pragma unroll
        for (int h = 0; h < 2; h++) {
            int row = rg * 16 + h * 8 + g;
            int col = cg * 32 + nb * 8 + cl;
            float v0 = d1[nb * 4 + h * 2], v1 = d1[nb * 4 + h * 2 + 1];
            float2 o;
            o.x = ns_s[row * 66 + col] + v0 * sigmf(v0);
            o.y = ns_s[row * 66 + col + 1] + v1 * sigmf(v1);
            *(float2*)(g_ns + (size_t)(node0 + row) * 64 + col) = o;
        }

    // ---------------- GEMM2: D2x[64,32] x3, warp tile 16r x 16c ----------------
    const ull* W2h = (const ull*)g_W2h;
    const ull* W2l = (const ull*)g_W2l;
    float d2[24];   // [x][nb][4]
#pragma unroll
    for (int q = 0; q < 24; q++) d2[q] = 0.f;

#pragma unroll 1
    for (int c = 0; c < 256; c++) {
        size_t wb = ((size_t)(L * 256 + c) * 4 + cg * 2) * 32 + lane;
        ull h0 = __ldg(W2h + wb), h1 = __ldg(W2h + wb + 32);
        ull l0 = __ldg(W2l + wb), l1 = __ldg(W2l + wb + 32);
        if (c < 128) {                               // usv: i=c>>1, n0=(c&1)*16
            const int i = c >> 1, n0 = (c & 1) * 16;
            ull u2[2];
            u2[0] = pack2(ns_s[R0 * 66 + i], ns_s[R0 * 66 + i]);
            u2[1] = pack2(ns_s[R1 * 66 + i], ns_s[R1 * 66 + i]);
#pragma unroll
            for (int x = 0; x < 3; x++) {
                uint32_t ah[4], al[4];
#pragma unroll
                for (int j = 0; j < 2; j++) {
                    const float* vp = av_s + (j ? R1 : R0) * 100 + x * 32 + n0;
                    ull pa = fmul2(u2[j], *(const ull*)(vp + cl));
                    ull pb = fmul2(u2[j], *(const ull*)(vp + cl + 8));
                    bsplit2(pa, ah[j], al[j]);
                    bsplit2(pb, ah[j + 2], al[j + 2]);
                }
                float* da = d2 + x * 8;
                mma_bf16(da, ah, (uint32_t)h0, (uint32_t)(h0 >> 32));
                mma_bf16(da, ah, (uint32_t)l0, (uint32_t)(l0 >> 32));
                mma_bf16(da, al, (uint32_t)h0, (uint32_t)(h0 >> 32));
                float* db = d2 + x * 8 + 4;
                mma_bf16(db, ah, (uint32_t)h1, (uint32_t)(h1 >> 32));
                mma_bf16(db, ah, (uint32_t)l1, (uint32_t)(l1 >> 32));
                mma_bf16(db, al, (uint32_t)h1, (uint32_t)(h1 >> 32));
            }
        } else {                                     // uvs: m2=cc>>2, j0=(cc&3)*16
            const int cc = c - 128, m2 = cc >> 2, j0 = (cc & 3) * 16;
            ull va[2], vb[2];
#pragma unroll
            for (int j = 0; j < 2; j++) {
                const float* vp = as_s + (j ? R1 : R0) * 66 + j0;
                va[j] = *(const ull*)(vp + cl);
                vb[j] = *(const ull*)(vp + cl + 8);
            }
#pragma unroll
            for (int x = 0; x < 3; x++) {
                uint32_t ah[4], al[4];
#pragma unroll
                for (int j = 0; j < 2; j++) {
                    float u = nv_s[(j ? R1 : R0) * 96 + m2 * 3 + x];
                    ull u2v = pack2(u, u);
                    bsplit2(fmul2(u2v, va[j]), ah[j], al[j]);
                    bsplit2(fmul2(u2v, vb[j]), ah[j + 2], al[j + 2]);
                }
                float* da = d2 + x * 8;
                mma_bf16(da, ah, (uint32_t)h0, (uint32_t)(h0 >> 32));
                mma_bf16(da, ah, (uint32_t)l0, (uint32_t)(l0 >> 32));
                mma_bf16(da, al, (uint32_t)h0, (uint32_t)(h0 >> 32));
                float* db = d2 + x * 8 + 4;
                mma_bf16(db, ah, (uint32_t)h1, (uint32_t)(h1 >> 32));
                mma_bf16(db, ah, (uint32_t)l1, (uint32_t)(l1 >> 32));
                mma_bf16(db, al, (uint32_t)h1, (uint32_t)(h1 >> 32));
            }
        }
    }

    // ---- gate mean + epilogue-B ----
    {
        float rs[2];
#pragma unroll
        for (int h = 0; h < 2; h++) {
            float s = 0.f;
#pragma unroll
            for (int x = 0; x < 3; x++)
#pragma unroll
                for (int nb = 0; nb < 2; nb++)
                    s += d2[x * 8 + nb * 4 + h * 2] + d2[x * 8 + nb * 4 + h * 2 + 1];
            rs[h] = s;
        }
#pragma unroll
        for (int h = 0; h < 2; h++) {
            rs[h] += __shfl_xor_sync(0xffffffffu, rs[h], 1);
            rs[h] += __shfl_xor_sync(0xffffffffu, rs[h], 2);
        }
        if ((lane & 3) == 0) {
            red[cg * 64 + rg * 16 + g] = rs[0];
            red[cg * 64 + rg * 16 + 8 + g] = rs[1];
        }
        __syncthreads();
#pragma unroll
        for (int h = 0; h < 2; h++) {
            int row = rg * 16 + h * 8 + g;
            float mean = (red[row] + red[64 + row]) * (1.0f / 96.0f);
#pragma unroll
            for (int x = 0; x < 3; x++)
#pragma unroll
                for (int nb = 0; nb < 2; nb++)
#pragma unroll
                    for (int q2 = 0; q2 < 2; q2++) {
                        int o = cg * 16 + nb * 8 + cl + q2, f = o * 3 + x;
                        float v = d2[x * 8 + nb * 4 + h * 2 + q2];
                        float gt = sigmf(mean * __ldg(guw + f) + __ldg(gub + f));
                        g_nv[(size_t)(node0 + row) * 96 + f] = nv_s[row * 96 + f] + v * gt;
                    }
        }
    }
}

// ================= k_out =================
__global__ __launch_bounds__(256) void k_out(const float* __restrict__ Wout, float* __restrict__ out) {
    __shared__ float s_w[32 * 256], s_ns[16 * 64];
    const int tid = threadIdx.x, node0 = blockIdx.x * 16;
#pragma unroll
    for (int r = 0; r < 4; r++) {
        int lin = tid + r * 256, t = lin >> 6, i = lin & 63;
        s_ns[t * 64 + i] = g_ns[(size_t)(node0 + t) * 64 + i];
    }
    float acc[16];
#pragma unroll
    for (int t = 0; t < 16; t++) acc[t] = 0.f;
    for (int ic = 0; ic < 2; ic++) {
        __syncthreads();
        const float4* wg = (const float4*)(Wout + (size_t)ic * 8192);
        float4* w4 = (float4*)s_w;
#pragma unroll
        for (int r = 0; r < 8; r++) w4[tid + r * 256] = wg[tid + r * 256];
        __syncthreads();
#pragma unroll 8
        for (int i = 0; i < 32; i++) {
            float w = s_w[i * 256 + tid];
#pragma unroll
            for (int t = 0; t < 16; t++) acc[t] += s_ns[t * 64 + ic * 32 + i] * w;
        }
    }
#pragma unroll
    for (int t = 0; t < 16; t++) out[(size_t)(node0 + t) * 256 + tid] = acc[t] * INV8;
}

extern "C" void kernel_launch(void* const* d_in, const int* in_sizes, int n_in,
                              void* d_out, int out_size) {
    const float* x    = (const float*)d_in[0];
    const float* eattr= (const float*)d_in[1];
    const float* Win  = (const float*)d_in[2];
    const float* Wout = (const float*)d_in[3];
    const float* Wss  = (const float*)d_in[4];
    const float* Wvv0 = (const float*)d_in[5];
    const float* Wsv  = (const float*)d_in[6];
    const float* Wvs  = (const float*)d_in[7];
    const float* gmw  = (const float*)d_in[8];
    const float* gmb  = (const float*)d_in[9];
    const float* Wuss = (const float*)d_in[10];
    const float* Wuvv = (const float*)d_in[11];
    const float* Wusv = (const float*)d_in[12];
    const float* Wuvs = (const float*)d_in[13];
    const float* guw  = (const float*)d_in[14];
    const float* gub  = (const float*)d_in[15];
    const int*   eidx = (const int*)d_in[16];
    float* out = (float*)d_out;

    void *p_nv = 0, *p_as = 0, *p_av = 0;
    cudaGetSymbolAddress(&p_nv, g_nv);
    cudaGetSymbolAddress(&p_as, g_as);
    cudaGetSymbolAddress(&p_av, g_av);
    cudaFuncSetAttribute(k_bilin_mma, cudaFuncAttributeMaxDynamicSharedMemorySize, MMA_SMEM);

    cudaMemsetAsync(p_nv, 0, sizeof(float) * NN * 96, 0);
    k_prep<<<2304, 256>>>(Wuss, Wuvv, Wusv, Wuvs);
    k_in<<<NN / 32, 256>>>(x, Win);
    for (int l = 0; l < 2; l++) {
        k_feat<<<NN / 8, 256>>>(Wss + l * 4096, Wvv0 + l * 2048, Wsv + l * 2048, Wvs + l * 1024);
        cudaMemsetAsync(p_as, 0, sizeof(float) * NN * 64, 0);
        cudaMemsetAsync(p_av, 0, sizeof(float) * NN * 96, 0);
        k_edge<<<EE / 8, 256>>>(eattr, eidx, gmw + l * 96, gmb + l * 96);
        k_bilin_mma<<<NN / 64, 256, MMA_SMEM>>>(l, guw + l * 96, gub + l * 96);
    }
    k_out<<<NN / 16, 256>>>(Wout, out);
}